// round 8
// baseline (speedup 1.0000x reference)
#include <cuda_runtime.h>
#include <cstdint>

#define T_DIM     2000
#define KFR       400
#define KD        400
#define A_DIM     100
#define NB        (KFR / 16)       // 25 stages of 16 rows per block (1 t-slab)
#define GRID      T_DIM            // one block per t
#define STAGES    5
#define STAGE_X   6400             // 16 rows * 400B
#define STAGE_SZ  6528             // + 64B mask + pad (16B aligned)
#define NCHUNK    404              // 400 X-chunks + 4 mask-chunks of 16B
#define EPSF      1e-24f

typedef unsigned long long u64;

__device__ __forceinline__ u64 pack2(float lo, float hi) {
    u64 r; asm("mov.b64 %0, {%1, %2};" : "=l"(r) : "f"(lo), "f"(hi)); return r;
}
__device__ __forceinline__ void unpack2(u64 v, float& lo, float& hi) {
    asm("mov.b64 {%0, %1}, %2;" : "=f"(lo), "=f"(hi) : "l"(v));
}
__device__ __forceinline__ u64 ffma2(u64 a, u64 b, u64 c) {
    u64 d; asm("fma.rn.f32x2 %0, %1, %2, %3;" : "=l"(d) : "l"(a), "l"(b), "l"(c));
    return d;
}
__device__ __forceinline__ void cp16(uint32_t sdst, const void* gsrc) {
    asm volatile("cp.async.cg.shared.global [%0], [%1], 16;"
                 :: "r"(sdst), "l"(gsrc));
}

// Accumulators: [0..99]=Ga, [100..199]=Ha, [200]=P1, [201]=P2. Self-cleaning.
__device__ float d_acc[2 * A_DIM + 2];
__device__ unsigned int d_done;

// One block per time slab t (contiguous 160KB of X). A 5-deep cp.async smem
// ring keeps ~26KB of loads in flight per block, fully decoupling HBM from
// the compute chain (LDS replaces LDG in the dependency path). Packed
// butterfly: 9 shfl reduce 4 row-dots into disjoint 8-lane groups so the
// exp/log/div runs once per group. phi_fr folded at row level; the last
// block performs the scalar finalize inline.
__global__ __launch_bounds__(128) void mmdglm_main(
    const float* __restrict__ tg, const int* __restrict__ mask,
    const float* __restrict__ X, const float* __restrict__ theta,
    const float* __restrict__ phi_fr, const float* __restrict__ phi_d,
    float* __restrict__ out)
{
    __shared__ __align__(16) char s_pipe[STAGES * STAGE_SZ];
    __shared__ float sga[4][A_DIM];
    __shared__ float sha[4][A_DIM];
    __shared__ float sp[4][2];

    const int warp  = threadIdx.x >> 5;
    const int lane  = threadIdx.x & 31;
    const int tid   = threadIdx.x;
    const float dt  = tg[1] - tg[0];
    const unsigned FULL = 0xffffffffu;
    const u64 Z64 = 0ull;

    const char* gX = (const char*)X    + (size_t)blockIdx.x * (KFR * A_DIM * 4);
    const char* gM = (const char*)mask + (size_t)blockIdx.x * (KFR * 4);
    const uint32_t pipe_b = (uint32_t)__cvta_generic_to_shared(s_pipe);

    // theta packed as f32x2 pairs (loop-invariant)
    u64 th01 = Z64, th23 = Z64;
    if (lane < 25) {
        float4 th = __ldg(((const float4*)theta) + lane);
        th01 = pack2(th.x, th.y);
        th23 = pack2(th.z, th.w);
    }

    // packed-butterfly group -> row: lanes 0-7 r0, 8-15 r2, 16-23 r1, 24-31 r3
    const int myrow = (((lane >> 3) & 1) << 1) | ((lane >> 4) & 1);

    u64 Ga01 = Z64, Ga23 = Z64, Ha01 = Z64, Ha23 = Z64;
    float p1acc = 0.f, p2acc = 0.f;

    // ---- producer helper: stage s -> slot s%STAGES ----
    auto issue_stage = [&](int s) {
        const uint32_t slot = pipe_b + (uint32_t)(s % STAGES) * STAGE_SZ;
        #pragma unroll
        for (int it = 0; it < 4; it++) {
            const int c = tid + it * 128;
            if (c < 400) {
                cp16(slot + c * 16, gX + (size_t)s * STAGE_X + c * 16);
            } else if (c < NCHUNK) {
                cp16(slot + STAGE_X + (c - 400) * 16, gM + s * 64 + (c - 400) * 16);
            }
        }
    };

    // prologue: fill 4 stages
    #pragma unroll
    for (int s = 0; s < 4; s++) {
        issue_stage(s);
        asm volatile("cp.async.commit_group;");
    }

    #pragma unroll 1
    for (int g = 0; g < NB; g++) {
        asm volatile("cp.async.wait_group 3;");
        __syncthreads();   // slot (g-1)%5 fully consumed by all warps; g ready

        if (g + 4 < NB) issue_stage(g + 4);
        asm volatile("cp.async.commit_group;");

        const char* slot_p = s_pipe + (g % STAGES) * STAGE_SZ;
        const char* rows_p = slot_p + (warp * 4) * 400;

        ulonglong2 z2; z2.x = 0ull; z2.y = 0ull;
        ulonglong2 c0 = z2, c1 = z2, c2 = z2, c3 = z2;
        if (lane < 25) {
            c0 = *(const ulonglong2*)(rows_p            + lane * 16);
            c1 = *(const ulonglong2*)(rows_p + 400      + lane * 16);
            c2 = *(const ulonglong2*)(rows_p + 800      + lane * 16);
            c3 = *(const ulonglong2*)(rows_p + 1200     + lane * 16);
        }
        const int m = *(const int*)(slot_p + STAGE_X + (warp * 4 + myrow) * 4);

        const int kbase = g * 16 + warp * 4;
        const float pf0 = __ldg(phi_fr + kbase);
        const float pf1 = __ldg(phi_fr + kbase + 1);
        const float pf2 = __ldg(phi_fr + kbase + 2);
        const float pf3 = __ldg(phi_fr + kbase + 3);

        float p0, p1, p2, p3;
        {
            float lo, hi;
            unpack2(ffma2(c0.x, th01, ffma2(c0.y, th23, Z64)), lo, hi); p0 = lo + hi;
            unpack2(ffma2(c1.x, th01, ffma2(c1.y, th23, Z64)), lo, hi); p1 = lo + hi;
            unpack2(ffma2(c2.x, th01, ffma2(c2.y, th23, Z64)), lo, hi); p2 = lo + hi;
            unpack2(ffma2(c3.x, th01, ffma2(c3.y, th23, Z64)), lo, hi); p3 = lo + hi;
        }

        // Packed butterfly: 9 shfl reduce all 4 rows.
        float u0 = __shfl_xor_sync(FULL, p0, 16);
        float u1 = __shfl_xor_sync(FULL, p1, 16);
        float w01 = (lane & 16) ? (p1 + u1) : (p0 + u0);
        float u2 = __shfl_xor_sync(FULL, p2, 16);
        float u3 = __shfl_xor_sync(FULL, p3, 16);
        float w23 = (lane & 16) ? (p3 + u3) : (p2 + u2);
        float v01 = __shfl_xor_sync(FULL, w01, 8);
        float v23 = __shfl_xor_sync(FULL, w23, 8);
        float v = (lane & 8) ? (w23 + v23) : (w01 + v01);
        v += __shfl_xor_sync(FULL, v, 4);
        v += __shfl_xor_sync(FULL, v, 2);
        v += __shfl_xor_sync(FULL, v, 1);
        // v = dot of row (g*16 + warp*4 + myrow)

        const float r   = __expf(v);            // non_linearity = exp
        const float dtr = dt * r;
        float w, llc;
        if (m) {
            // 1 - e^-dtr = (E-1)/E  =>  llc = log(E-1) - dtr  (one exp)
            const float Em1 = __expf(dtr) - 1.0f;
            w   = __fdividef(dtr, Em1 - EPSF);
            llc = __logf(Em1 + EPSF) - dtr;
        } else {
            w   = -dtr;
            llc = -dtr;
        }
        const float pfmy = (myrow == 0) ? pf0 : (myrow == 1) ? pf1
                         : (myrow == 2) ? pf2 : pf3;
        p1acc += pfmy * llc;                    // 8x redundant; /8 at epilogue
        p2acc += pfmy * pfmy * llc;

        const float w0 = __shfl_sync(FULL, w, 0);
        const float w1 = __shfl_sync(FULL, w, 16);
        const float w2 = __shfl_sync(FULL, w, 8);
        const float w3 = __shfl_sync(FULL, w, 24);

        const float a0 = pf0 * w0, a1 = pf1 * w1, a2 = pf2 * w2, a3 = pf3 * w3;
        const u64 A0 = pack2(a0, a0), A1 = pack2(a1, a1);
        const u64 A2 = pack2(a2, a2), A3 = pack2(a3, a3);
        const u64 H0 = pack2(pf0 * a0, pf0 * a0), H1 = pack2(pf1 * a1, pf1 * a1);
        const u64 H2 = pack2(pf2 * a2, pf2 * a2), H3 = pack2(pf3 * a3, pf3 * a3);

        Ga01 = ffma2(A0, c0.x, Ga01); Ga23 = ffma2(A0, c0.y, Ga23);
        Ga01 = ffma2(A1, c1.x, Ga01); Ga23 = ffma2(A1, c1.y, Ga23);
        Ga01 = ffma2(A2, c2.x, Ga01); Ga23 = ffma2(A2, c2.y, Ga23);
        Ga01 = ffma2(A3, c3.x, Ga01); Ga23 = ffma2(A3, c3.y, Ga23);
        Ha01 = ffma2(H0, c0.x, Ha01); Ha23 = ffma2(H0, c0.y, Ha23);
        Ha01 = ffma2(H1, c1.x, Ha01); Ha23 = ffma2(H1, c1.y, Ha23);
        Ha01 = ffma2(H2, c2.x, Ha01); Ha23 = ffma2(H2, c2.y, Ha23);
        Ha01 = ffma2(H3, c3.x, Ha01); Ha23 = ffma2(H3, c3.y, Ha23);
    }

    #pragma unroll
    for (int o = 16; o; o >>= 1) {
        p1acc += __shfl_xor_sync(FULL, p1acc, o);
        p2acc += __shfl_xor_sync(FULL, p2acc, o);
    }
    p1acc *= 0.125f; p2acc *= 0.125f;

    if (lane < 25) {
        float g0, g1, g2, g3, h0, h1, h2, h3;
        unpack2(Ga01, g0, g1); unpack2(Ga23, g2, g3);
        unpack2(Ha01, h0, h1); unpack2(Ha23, h2, h3);
        *(float4*)&sga[warp][lane * 4] = make_float4(g0, g1, g2, g3);
        *(float4*)&sha[warp][lane * 4] = make_float4(h0, h1, h2, h3);
    }
    if (lane == 0) { sp[warp][0] = p1acc; sp[warp][1] = p2acc; }
    __syncthreads();

    if (tid < A_DIM) {
        const float ga = sga[0][tid] + sga[1][tid] + sga[2][tid] + sga[3][tid];
        const float ha = sha[0][tid] + sha[1][tid] + sha[2][tid] + sha[3][tid];
        atomicAdd(&d_acc[tid],         ga);
        atomicAdd(&d_acc[A_DIM + tid], ha);
    }
    if (tid == 0)
        atomicAdd(&d_acc[2 * A_DIM],     sp[0][0] + sp[1][0] + sp[2][0] + sp[3][0]);
    if (tid == 1)
        atomicAdd(&d_acc[2 * A_DIM + 1], sp[0][1] + sp[1][1] + sp[2][1] + sp[3][1]);

    // ---- last-block-done fused finalize ----
    __threadfence();
    __shared__ bool amlast;
    if (tid == 0) amlast = (atomicAdd(&d_done, 1u) == (unsigned)(gridDim.x - 1));
    __syncthreads();
    if (!amlast) return;

    volatile float* vacc = d_acc;
    float Ga = 0.f, Ha = 0.f;
    if (tid < A_DIM) { Ga = vacc[tid]; Ha = vacc[A_DIM + tid]; }
    const float P1 = vacc[2 * A_DIM], P2 = vacc[2 * A_DIM + 1];

    float b0 = 0.f, b1 = 0.f, b2 = 0.f, b3 = 0.f;
    for (int i = tid; i < KFR; i += 128) {
        const float pfv = phi_fr[i], pdv = phi_d[i];
        b0 += pfv; b1 += pfv * pfv; b2 += pdv; b3 += pdv * pdv;
    }
    #pragma unroll
    for (int o = 16; o; o >>= 1) {
        b0 += __shfl_xor_sync(FULL, b0, o);
        b1 += __shfl_xor_sync(FULL, b1, o);
        b2 += __shfl_xor_sync(FULL, b2, o);
        b3 += __shfl_xor_sync(FULL, b3, o);
    }
    __shared__ float shp[4][4];
    __shared__ float sc[4];
    if (lane == 0) { shp[warp][0] = b0; shp[warp][1] = b1;
                     shp[warp][2] = b2; shp[warp][3] = b3; }
    __syncthreads();

    // clean state for the next graph replay
    if (tid < A_DIM) { d_acc[tid] = 0.f; d_acc[A_DIM + tid] = 0.f; }
    if (tid == A_DIM) { d_acc[2 * A_DIM] = 0.f; d_acc[2 * A_DIM + 1] = 0.f;
                        d_done = 0u; }

    if (tid < 4) sc[tid] = shp[0][tid] + shp[1][tid] + shp[2][tid] + shp[3][tid];
    __syncthreads();

    const float S_fr = sc[0], Q_fr = sc[1], S_d = sc[2], Q_d = sc[3];
    const float n_fr = 0.5f * (float)KFR * (float)(KFR - 1);
    const float n_d  = 0.5f * (float)KD  * (float)(KD - 1);
    const float inv_kdkfr = 1.0f / ((float)KD * (float)KFR);

    if (tid == 0) {
        out[0] = (P1 * S_fr - P2) / n_fr - 2.0f * S_d * P1 * inv_kdkfr;
        out[1 + A_DIM] = (S_d * S_d - Q_d) / (2.0f * n_d)
                       + (S_fr * S_fr - Q_fr) / (2.0f * n_fr)
                       - 2.0f * S_d * S_fr * inv_kdkfr;
    }
    if (tid < A_DIM) {
        out[1 + tid] = (S_fr * Ga - Ha) / n_fr - 2.0f * S_d * Ga * inv_kdkfr;
    }
}

extern "C" void kernel_launch(void* const* d_in, const int* in_sizes, int n_in,
                              void* d_out, int out_size) {
    const float* t      = (const float*)d_in[0];
    const int*   mask   = (const int*)  d_in[1];
    const float* X      = (const float*)d_in[2];
    const float* theta  = (const float*)d_in[3];
    const float* phi_d  = (const float*)d_in[4];
    const float* phi_fr = (const float*)d_in[5];
    float* out = (float*)d_out;

    mmdglm_main<<<GRID, 128>>>(t, mask, X, theta, phi_fr, phi_d, out);
}

// round 9
// speedup vs baseline: 1.0757x; 1.0757x over previous
#include <cuda_runtime.h>

#define T_DIM   2000
#define KFR     400
#define KD      400
#define A_DIM   100
#define SLABS   2                      // t-slabs per block (800 contiguous rows)
#define GRID    (T_DIM / SLABS)        // 1000 blocks
#define NIT     25                     // 800 rows / (4 warps * 8 rows)
#define EPSF    1e-24f

typedef unsigned long long u64;

__device__ __forceinline__ u64 pack2(float lo, float hi) {
    u64 r; asm("mov.b64 %0, {%1, %2};" : "=l"(r) : "f"(lo), "f"(hi)); return r;
}
__device__ __forceinline__ void unpack2(u64 v, float& lo, float& hi) {
    asm("mov.b64 {%0, %1}, %2;" : "=f"(lo), "=f"(hi) : "l"(v));
}
__device__ __forceinline__ u64 ffma2(u64 a, u64 b, u64 c) {
    u64 d; asm("fma.rn.f32x2 %0, %1, %2, %3;" : "=l"(d) : "l"(a), "l"(b), "l"(c));
    return d;
}

// Accumulators: [0..99]=Ga, [100..199]=Ha, [200]=P1, [201]=P2. Self-cleaning.
__device__ float d_acc[2 * A_DIM + 2];
__device__ unsigned int d_done;

// One block per 2 adjacent t-slabs (contiguous 320KB of X). Each warp owns
// 8 rows per iteration: a 3-level PACKING butterfly (8+4+2 shfl) leaves the
// 8 row-dots in disjoint 4-lane groups, 2 shared levels finish them — 16
// shfl per 8 rows and ONE exp/log/div warp-op serves all 8 rows. The whole
// ~350cyc serial chain (butterfly+transcendental+broadcast) is paid once per
// 8 rows instead of per 4. Double-buffered prefetch (8 LDG.128 in flight),
// FFMA2 accumulation, phi folded at row level, fused last-block finalize.
__global__ __launch_bounds__(128) void mmdglm_main(
    const float* __restrict__ tg, const int* __restrict__ mask,
    const float* __restrict__ X, const float* __restrict__ theta,
    const float* __restrict__ phi_fr, const float* __restrict__ phi_d,
    float* __restrict__ out)
{
    const int warp  = threadIdx.x >> 5;
    const int lane  = threadIdx.x & 31;
    const int tid   = threadIdx.x;
    const float dt  = tg[1] - tg[0];
    const unsigned FULL = 0xffffffffu;
    const u64 Z64 = 0ull;

    // theta packed as f32x2 pairs (loop-invariant)
    u64 th01 = Z64, th23 = Z64;
    if (lane < 25) {
        float4 th = __ldg(((const float4*)theta) + lane);
        th01 = pack2(th.x, th.y);
        th23 = pack2(th.z, th.w);
    }

    // 4-lane group -> row after the packed butterfly:
    // row = bit4(lane) | bit3(lane)<<1 | bit2(lane)<<2
    const int myrow = ((lane >> 4) & 1) | (((lane >> 3) & 1) << 1)
                    | (((lane >> 2) & 1) << 2);

    u64 Ga01 = Z64, Ga23 = Z64, Ha01 = Z64, Ha23 = Z64;
    float p1acc = 0.f, p2acc = 0.f;

    const float* slab = X    + (size_t)(blockIdx.x * SLABS) * KFR * A_DIM;
    const int*   mrow = mask + (size_t)(blockIdx.x * SLABS) * KFR;

    ulonglong2 z2; z2.x = 0ull; z2.y = 0ull;
    ulonglong2 c0 = z2, c1 = z2, c2 = z2, c3 = z2,
               c4 = z2, c5 = z2, c6 = z2, c7 = z2;
    {
        const float* rowp = slab + (warp * 8) * A_DIM;
        if (lane < 25) {
            c0 = __ldg((const ulonglong2*)(rowp)             + lane);
            c1 = __ldg((const ulonglong2*)(rowp + A_DIM)     + lane);
            c2 = __ldg((const ulonglong2*)(rowp + 2 * A_DIM) + lane);
            c3 = __ldg((const ulonglong2*)(rowp + 3 * A_DIM) + lane);
            c4 = __ldg((const ulonglong2*)(rowp + 4 * A_DIM) + lane);
            c5 = __ldg((const ulonglong2*)(rowp + 5 * A_DIM) + lane);
            c6 = __ldg((const ulonglong2*)(rowp + 6 * A_DIM) + lane);
            c7 = __ldg((const ulonglong2*)(rowp + 7 * A_DIM) + lane);
        }
    }
    int mcur = __ldg(mrow + warp * 8 + myrow);

    #pragma unroll 1
    for (int g = 0; g < NIT; g++) {
        const int grbase = g * 32 + warp * 8;          // global row 0..799

        ulonglong2 n0 = z2, n1 = z2, n2 = z2, n3 = z2,
                   n4 = z2, n5 = z2, n6 = z2, n7 = z2;
        int mnext = 0;
        if (g + 1 < NIT) {
            const int grn = grbase + 32;
            const float* rowp = slab + (size_t)grn * A_DIM;
            if (lane < 25) {
                n0 = __ldg((const ulonglong2*)(rowp)             + lane);
                n1 = __ldg((const ulonglong2*)(rowp + A_DIM)     + lane);
                n2 = __ldg((const ulonglong2*)(rowp + 2 * A_DIM) + lane);
                n3 = __ldg((const ulonglong2*)(rowp + 3 * A_DIM) + lane);
                n4 = __ldg((const ulonglong2*)(rowp + 4 * A_DIM) + lane);
                n5 = __ldg((const ulonglong2*)(rowp + 5 * A_DIM) + lane);
                n6 = __ldg((const ulonglong2*)(rowp + 6 * A_DIM) + lane);
                n7 = __ldg((const ulonglong2*)(rowp + 7 * A_DIM) + lane);
            }
            mnext = __ldg(mrow + grn + myrow);
        }

        const int kbase = (grbase >= KFR) ? (grbase - KFR) : grbase;
        const float pf0 = __ldg(phi_fr + kbase);
        const float pf1 = __ldg(phi_fr + kbase + 1);
        const float pf2 = __ldg(phi_fr + kbase + 2);
        const float pf3 = __ldg(phi_fr + kbase + 3);
        const float pf4 = __ldg(phi_fr + kbase + 4);
        const float pf5 = __ldg(phi_fr + kbase + 5);
        const float pf6 = __ldg(phi_fr + kbase + 6);
        const float pf7 = __ldg(phi_fr + kbase + 7);

        // dots via f32x2
        float p0, p1, p2, p3, p4, p5, p6, p7;
        {
            float lo, hi;
            unpack2(ffma2(c0.x, th01, ffma2(c0.y, th23, Z64)), lo, hi); p0 = lo + hi;
            unpack2(ffma2(c1.x, th01, ffma2(c1.y, th23, Z64)), lo, hi); p1 = lo + hi;
            unpack2(ffma2(c2.x, th01, ffma2(c2.y, th23, Z64)), lo, hi); p2 = lo + hi;
            unpack2(ffma2(c3.x, th01, ffma2(c3.y, th23, Z64)), lo, hi); p3 = lo + hi;
            unpack2(ffma2(c4.x, th01, ffma2(c4.y, th23, Z64)), lo, hi); p4 = lo + hi;
            unpack2(ffma2(c5.x, th01, ffma2(c5.y, th23, Z64)), lo, hi); p5 = lo + hi;
            unpack2(ffma2(c6.x, th01, ffma2(c6.y, th23, Z64)), lo, hi); p6 = lo + hi;
            unpack2(ffma2(c7.x, th01, ffma2(c7.y, th23, Z64)), lo, hi); p7 = lo + hi;
        }

        // Packed butterfly: 16 shfl reduce all 8 rows.
        // L16: 4 pairs
        float s;
        s = __shfl_xor_sync(FULL, p0, 16); float q01a = p0 + s;
        s = __shfl_xor_sync(FULL, p1, 16); float q01b = p1 + s;
        float q01 = (lane & 16) ? q01b : q01a;
        s = __shfl_xor_sync(FULL, p2, 16); float q23a = p2 + s;
        s = __shfl_xor_sync(FULL, p3, 16); float q23b = p3 + s;
        float q23 = (lane & 16) ? q23b : q23a;
        s = __shfl_xor_sync(FULL, p4, 16); float q45a = p4 + s;
        s = __shfl_xor_sync(FULL, p5, 16); float q45b = p5 + s;
        float q45 = (lane & 16) ? q45b : q45a;
        s = __shfl_xor_sync(FULL, p6, 16); float q67a = p6 + s;
        s = __shfl_xor_sync(FULL, p7, 16); float q67b = p7 + s;
        float q67 = (lane & 16) ? q67b : q67a;
        // L8: 2 pairs
        s = __shfl_xor_sync(FULL, q01, 8); float r03a = q01 + s;
        s = __shfl_xor_sync(FULL, q23, 8); float r03b = q23 + s;
        float r03 = (lane & 8) ? r03b : r03a;
        s = __shfl_xor_sync(FULL, q45, 8); float r47a = q45 + s;
        s = __shfl_xor_sync(FULL, q67, 8); float r47b = q67 + s;
        float r47 = (lane & 8) ? r47b : r47a;
        // L4: 1 pair
        s = __shfl_xor_sync(FULL, r03, 4); float va = r03 + s;
        s = __shfl_xor_sync(FULL, r47, 4); float vb = r47 + s;
        float v = (lane & 4) ? vb : va;
        // shared tail
        v += __shfl_xor_sync(FULL, v, 2);
        v += __shfl_xor_sync(FULL, v, 1);
        // v = dot of row (grbase + myrow); rows in 4-lane groups:
        // lanes0-3:r0 4-7:r4 8-11:r2 12-15:r6 16-19:r1 20-23:r5 24-27:r3 28-31:r7

        const float r   = __expf(v);            // non_linearity = exp
        const float dtr = dt * r;
        float w, llc;
        if (mcur) {
            // 1 - e^-dtr = (E-1)/E  =>  llc = log(E-1) - dtr  (one exp)
            const float Em1 = __expf(dtr) - 1.0f;
            w   = __fdividef(dtr, Em1 - EPSF);
            llc = __logf(Em1 + EPSF) - dtr;
        } else {
            w   = -dtr;
            llc = -dtr;
        }
        const float pfmy = (myrow == 0) ? pf0 : (myrow == 1) ? pf1
                         : (myrow == 2) ? pf2 : (myrow == 3) ? pf3
                         : (myrow == 4) ? pf4 : (myrow == 5) ? pf5
                         : (myrow == 6) ? pf6 : pf7;
        p1acc += pfmy * llc;                    // 4x redundant; /4 at epilogue
        p2acc += pfmy * pfmy * llc;

        const float w0 = __shfl_sync(FULL, w, 0);
        const float w1 = __shfl_sync(FULL, w, 16);
        const float w2 = __shfl_sync(FULL, w, 8);
        const float w3 = __shfl_sync(FULL, w, 24);
        const float w4 = __shfl_sync(FULL, w, 4);
        const float w5 = __shfl_sync(FULL, w, 20);
        const float w6 = __shfl_sync(FULL, w, 12);
        const float w7 = __shfl_sync(FULL, w, 28);

        const float a0 = pf0 * w0, a1 = pf1 * w1, a2 = pf2 * w2, a3 = pf3 * w3;
        const float a4 = pf4 * w4, a5 = pf5 * w5, a6 = pf6 * w6, a7 = pf7 * w7;
        const u64 A0 = pack2(a0, a0), A1 = pack2(a1, a1);
        const u64 A2 = pack2(a2, a2), A3 = pack2(a3, a3);
        const u64 A4 = pack2(a4, a4), A5 = pack2(a5, a5);
        const u64 A6 = pack2(a6, a6), A7 = pack2(a7, a7);
        const u64 H0 = pack2(pf0 * a0, pf0 * a0), H1 = pack2(pf1 * a1, pf1 * a1);
        const u64 H2 = pack2(pf2 * a2, pf2 * a2), H3 = pack2(pf3 * a3, pf3 * a3);
        const u64 H4 = pack2(pf4 * a4, pf4 * a4), H5 = pack2(pf5 * a5, pf5 * a5);
        const u64 H6 = pack2(pf6 * a6, pf6 * a6), H7 = pack2(pf7 * a7, pf7 * a7);

        Ga01 = ffma2(A0, c0.x, Ga01); Ga23 = ffma2(A0, c0.y, Ga23);
        Ga01 = ffma2(A1, c1.x, Ga01); Ga23 = ffma2(A1, c1.y, Ga23);
        Ga01 = ffma2(A2, c2.x, Ga01); Ga23 = ffma2(A2, c2.y, Ga23);
        Ga01 = ffma2(A3, c3.x, Ga01); Ga23 = ffma2(A3, c3.y, Ga23);
        Ga01 = ffma2(A4, c4.x, Ga01); Ga23 = ffma2(A4, c4.y, Ga23);
        Ga01 = ffma2(A5, c5.x, Ga01); Ga23 = ffma2(A5, c5.y, Ga23);
        Ga01 = ffma2(A6, c6.x, Ga01); Ga23 = ffma2(A6, c6.y, Ga23);
        Ga01 = ffma2(A7, c7.x, Ga01); Ga23 = ffma2(A7, c7.y, Ga23);
        Ha01 = ffma2(H0, c0.x, Ha01); Ha23 = ffma2(H0, c0.y, Ha23);
        Ha01 = ffma2(H1, c1.x, Ha01); Ha23 = ffma2(H1, c1.y, Ha23);
        Ha01 = ffma2(H2, c2.x, Ha01); Ha23 = ffma2(H2, c2.y, Ha23);
        Ha01 = ffma2(H3, c3.x, Ha01); Ha23 = ffma2(H3, c3.y, Ha23);
        Ha01 = ffma2(H4, c4.x, Ha01); Ha23 = ffma2(H4, c4.y, Ha23);
        Ha01 = ffma2(H5, c5.x, Ha01); Ha23 = ffma2(H5, c5.y, Ha23);
        Ha01 = ffma2(H6, c6.x, Ha01); Ha23 = ffma2(H6, c6.y, Ha23);
        Ha01 = ffma2(H7, c7.x, Ha01); Ha23 = ffma2(H7, c7.y, Ha23);

        c0 = n0; c1 = n1; c2 = n2; c3 = n3;
        c4 = n4; c5 = n5; c6 = n6; c7 = n7; mcur = mnext;
    }

    #pragma unroll
    for (int o = 16; o; o >>= 1) {
        p1acc += __shfl_xor_sync(FULL, p1acc, o);
        p2acc += __shfl_xor_sync(FULL, p2acc, o);
    }
    p1acc *= 0.25f; p2acc *= 0.25f;

    __shared__ float sga[4][A_DIM];
    __shared__ float sha[4][A_DIM];
    __shared__ float sp[4][2];
    if (lane < 25) {
        float g0, g1, g2, g3, h0, h1, h2, h3;
        unpack2(Ga01, g0, g1); unpack2(Ga23, g2, g3);
        unpack2(Ha01, h0, h1); unpack2(Ha23, h2, h3);
        *(float4*)&sga[warp][lane * 4] = make_float4(g0, g1, g2, g3);
        *(float4*)&sha[warp][lane * 4] = make_float4(h0, h1, h2, h3);
    }
    if (lane == 0) { sp[warp][0] = p1acc; sp[warp][1] = p2acc; }
    __syncthreads();

    if (tid < A_DIM) {
        const float ga = sga[0][tid] + sga[1][tid] + sga[2][tid] + sga[3][tid];
        const float ha = sha[0][tid] + sha[1][tid] + sha[2][tid] + sha[3][tid];
        atomicAdd(&d_acc[tid],         ga);
        atomicAdd(&d_acc[A_DIM + tid], ha);
    }
    if (tid == 0)
        atomicAdd(&d_acc[2 * A_DIM],     sp[0][0] + sp[1][0] + sp[2][0] + sp[3][0]);
    if (tid == 1)
        atomicAdd(&d_acc[2 * A_DIM + 1], sp[0][1] + sp[1][1] + sp[2][1] + sp[3][1]);

    // ---- last-block-done fused finalize ----
    __threadfence();
    __shared__ bool amlast;
    if (tid == 0) amlast = (atomicAdd(&d_done, 1u) == (unsigned)(gridDim.x - 1));
    __syncthreads();
    if (!amlast) return;

    volatile float* vacc = d_acc;
    float Ga = 0.f, Ha = 0.f;
    if (tid < A_DIM) { Ga = vacc[tid]; Ha = vacc[A_DIM + tid]; }
    const float P1 = vacc[2 * A_DIM], P2 = vacc[2 * A_DIM + 1];

    float b0 = 0.f, b1 = 0.f, b2 = 0.f, b3 = 0.f;
    for (int i = tid; i < KFR; i += 128) {
        const float pfv = phi_fr[i], pdv = phi_d[i];
        b0 += pfv; b1 += pfv * pfv; b2 += pdv; b3 += pdv * pdv;
    }
    #pragma unroll
    for (int o = 16; o; o >>= 1) {
        b0 += __shfl_xor_sync(FULL, b0, o);
        b1 += __shfl_xor_sync(FULL, b1, o);
        b2 += __shfl_xor_sync(FULL, b2, o);
        b3 += __shfl_xor_sync(FULL, b3, o);
    }
    __shared__ float shp[4][4];
    __shared__ float sc[4];
    if (lane == 0) { shp[warp][0] = b0; shp[warp][1] = b1;
                     shp[warp][2] = b2; shp[warp][3] = b3; }
    __syncthreads();

    // clean state for the next graph replay
    if (tid < A_DIM) { d_acc[tid] = 0.f; d_acc[A_DIM + tid] = 0.f; }
    if (tid == A_DIM) { d_acc[2 * A_DIM] = 0.f; d_acc[2 * A_DIM + 1] = 0.f;
                        d_done = 0u; }

    if (tid < 4) sc[tid] = shp[0][tid] + shp[1][tid] + shp[2][tid] + shp[3][tid];
    __syncthreads();

    const float S_fr = sc[0], Q_fr = sc[1], S_d = sc[2], Q_d = sc[3];
    const float n_fr = 0.5f * (float)KFR * (float)(KFR - 1);
    const float n_d  = 0.5f * (float)KD  * (float)(KD - 1);
    const float inv_kdkfr = 1.0f / ((float)KD * (float)KFR);

    if (tid == 0) {
        out[0] = (P1 * S_fr - P2) / n_fr - 2.0f * S_d * P1 * inv_kdkfr;
        out[1 + A_DIM] = (S_d * S_d - Q_d) / (2.0f * n_d)
                       + (S_fr * S_fr - Q_fr) / (2.0f * n_fr)
                       - 2.0f * S_d * S_fr * inv_kdkfr;
    }
    if (tid < A_DIM) {
        out[1 + tid] = (S_fr * Ga - Ha) / n_fr - 2.0f * S_d * Ga * inv_kdkfr;
    }
}

extern "C" void kernel_launch(void* const* d_in, const int* in_sizes, int n_in,
                              void* d_out, int out_size) {
    const float* t      = (const float*)d_in[0];
    const int*   mask   = (const int*)  d_in[1];
    const float* X      = (const float*)d_in[2];
    const float* theta  = (const float*)d_in[3];
    const float* phi_d  = (const float*)d_in[4];
    const float* phi_fr = (const float*)d_in[5];
    float* out = (float*)d_out;

    mmdglm_main<<<GRID, 128>>>(t, mask, X, theta, phi_fr, phi_d, out);
}

// round 10
// speedup vs baseline: 1.3062x; 1.2143x over previous
#include <cuda_runtime.h>
#include <cstdint>

#define T_DIM    2000
#define KFR      400
#define KD       400
#define A_DIM    100
#define SLABS    2                      // t-slabs per block (800 rows, 320KB)
#define GRID     (T_DIM / SLABS)        // 1000 blocks
#define NIT      50                     // iterations of 16 rows (4 warps x 4)
#define STAGES   4
#define SLOT_X   1600                   // 4 rows * 400B, contiguous, 16B-aligned
#define SLOT_SZ  1664                   // + 16B mask + pad
#define TXB      1616u                  // expect_tx bytes per stage
#define EPSF     1e-24f

typedef unsigned long long u64;

__device__ __forceinline__ u64 pack2(float lo, float hi) {
    u64 r; asm("mov.b64 %0, {%1, %2};" : "=l"(r) : "f"(lo), "f"(hi)); return r;
}
__device__ __forceinline__ void unpack2(u64 v, float& lo, float& hi) {
    asm("mov.b64 {%0, %1}, %2;" : "=f"(lo), "=f"(hi) : "l"(v));
}
__device__ __forceinline__ u64 ffma2(u64 a, u64 b, u64 c) {
    u64 d; asm("fma.rn.f32x2 %0, %1, %2, %3;" : "=l"(d) : "l"(a), "l"(b), "l"(c));
    return d;
}
__device__ __forceinline__ void mbar_wait(uint32_t mbar, uint32_t parity) {
    asm volatile(
        "{\n\t.reg .pred P;\n\t"
        "W_%=:\n\t"
        "mbarrier.try_wait.parity.acquire.cta.shared::cta.b64 P, [%0], %1, 0x989680;\n\t"
        "@!P bra W_%=;\n\t}"
        :: "r"(mbar), "r"(parity) : "memory");
}

// Accumulators: [0..99]=Ga, [100..199]=Ha, [200]=P1, [201]=P2. Self-cleaning.
__device__ float d_acc[2 * A_DIM + 2];
__device__ unsigned int d_done;

// One block per 2 adjacent t-slabs (contiguous 320KB of X). Each warp runs a
// PRIVATE 4-deep cp.async.bulk pipeline: its 4 rows per iteration are one
// contiguous 1600B chunk, DMA'd into its own smem ring with a per-slot
// mbarrier. Single-producer single-consumer within the warp => no empty
// barrier, no __syncthreads in the loop; slot reissue trails its last read
// by >=3 iterations. Up to 3 stages in flight/warp at ZERO register cost —
// the latency*BW product is finally covered. Compute: packed butterfly
// (9 shfl / 4 rows, one exp/log/div warp-op per 4 rows), FFMA2 accumulation,
// phi_fr folded at row level, fused last-block finalize.
__global__ __launch_bounds__(128) void mmdglm_main(
    const float* __restrict__ tg, const int* __restrict__ mask,
    const float* __restrict__ X, const float* __restrict__ theta,
    const float* __restrict__ phi_fr, const float* __restrict__ phi_d,
    float* __restrict__ out)
{
    __shared__ __align__(16) char s_pipe[4 * STAGES * SLOT_SZ];   // ~26KB
    __shared__ __align__(8)  u64  s_mbar[4 * STAGES];
    __shared__ float sga[4][A_DIM];
    __shared__ float sha[4][A_DIM];
    __shared__ float sp[4][2];

    const int warp  = threadIdx.x >> 5;
    const int lane  = threadIdx.x & 31;
    const int tid   = threadIdx.x;
    const float dt  = tg[1] - tg[0];
    const unsigned FULL = 0xffffffffu;
    const u64 Z64 = 0ull;

    const char* gX = (const char*)X    + (size_t)(blockIdx.x * SLABS) * (KFR * A_DIM * 4);
    const char* gM = (const char*)mask + (size_t)(blockIdx.x * SLABS) * (KFR * 4);

    const uint32_t pipe_b = (uint32_t)__cvta_generic_to_shared(s_pipe);
    const uint32_t mbar_b = (uint32_t)__cvta_generic_to_shared(s_mbar);

    // init per-slot mbarriers (arrive count 1: the expect_tx arrival)
    if (tid < 4 * STAGES) {
        asm volatile("mbarrier.init.shared.b64 [%0], 1;"
                     :: "r"(mbar_b + tid * 8) : "memory");
    }
    asm volatile("fence.proxy.async.shared::cta;" ::: "memory");
    __syncthreads();

    // producer: issue stage for iteration g into slot g%STAGES (lane 0 only)
    auto issue = [&](int g) {
        const int slot = (g & (STAGES - 1));
        const uint32_t sd = pipe_b + (uint32_t)(warp * STAGES + slot) * SLOT_SZ;
        const uint32_t mb = mbar_b + (uint32_t)(warp * STAGES + slot) * 8;
        const size_t row0 = (size_t)(g * 16 + warp * 4);
        asm volatile("mbarrier.arrive.expect_tx.shared.b64 _, [%0], %1;"
                     :: "r"(mb), "r"(TXB) : "memory");
        asm volatile("cp.async.bulk.shared::cta.global.mbarrier::complete_tx::bytes"
                     " [%0], [%1], %2, [%3];"
                     :: "r"(sd), "l"(gX + row0 * 400), "n"(1600), "r"(mb) : "memory");
        asm volatile("cp.async.bulk.shared::cta.global.mbarrier::complete_tx::bytes"
                     " [%0], [%1], %2, [%3];"
                     :: "r"(sd + SLOT_X), "l"(gM + row0 * 4), "n"(16), "r"(mb) : "memory");
    };

    if (lane == 0) {
        #pragma unroll
        for (int s = 0; s < STAGES; s++) issue(s);
    }

    // theta packed as f32x2 pairs (loop-invariant)
    u64 th01 = Z64, th23 = Z64;
    if (lane < 25) {
        float4 th = __ldg(((const float4*)theta) + lane);
        th01 = pack2(th.x, th.y);
        th23 = pack2(th.z, th.w);
    }

    // packed-butterfly group -> row: lanes 0-7 r0, 8-15 r2, 16-23 r1, 24-31 r3
    const int myrow = (((lane >> 3) & 1) << 1) | ((lane >> 4) & 1);

    u64 Ga01 = Z64, Ga23 = Z64, Ha01 = Z64, Ha23 = Z64;
    float p1acc = 0.f, p2acc = 0.f;

    #pragma unroll 1
    for (int g = 0; g < NIT; g++) {
        const int slot = g & (STAGES - 1);
        const uint32_t mb = mbar_b + (uint32_t)(warp * STAGES + slot) * 8;
        mbar_wait(mb, (unsigned)((g >> 2) & 1));

        const char* sp_ = s_pipe + (warp * STAGES + slot) * SLOT_SZ;

        ulonglong2 z2; z2.x = 0ull; z2.y = 0ull;
        ulonglong2 c0 = z2, c1 = z2, c2 = z2, c3 = z2;
        if (lane < 25) {
            c0 = *(const ulonglong2*)(sp_         + lane * 16);
            c1 = *(const ulonglong2*)(sp_ + 400   + lane * 16);
            c2 = *(const ulonglong2*)(sp_ + 800   + lane * 16);
            c3 = *(const ulonglong2*)(sp_ + 1200  + lane * 16);
        }
        const int m = *(const int*)(sp_ + SLOT_X + myrow * 4);

        const int grbase = g * 16 + warp * 4;
        const int kbase = (grbase >= KFR) ? (grbase - KFR) : grbase;
        const float pf0 = __ldg(phi_fr + kbase);
        const float pf1 = __ldg(phi_fr + kbase + 1);
        const float pf2 = __ldg(phi_fr + kbase + 2);
        const float pf3 = __ldg(phi_fr + kbase + 3);

        float p0, p1, p2, p3;
        {
            float lo, hi;
            unpack2(ffma2(c0.x, th01, ffma2(c0.y, th23, Z64)), lo, hi); p0 = lo + hi;
            unpack2(ffma2(c1.x, th01, ffma2(c1.y, th23, Z64)), lo, hi); p1 = lo + hi;
            unpack2(ffma2(c2.x, th01, ffma2(c2.y, th23, Z64)), lo, hi); p2 = lo + hi;
            unpack2(ffma2(c3.x, th01, ffma2(c3.y, th23, Z64)), lo, hi); p3 = lo + hi;
        }

        // all lanes' LDS issued; safe for lane 0 to queue the slot reissue
        __syncwarp();
        if (lane == 0 && g + STAGES < NIT) issue(g + STAGES);

        // Packed butterfly: 9 shfl reduce all 4 rows.
        float u0 = __shfl_xor_sync(FULL, p0, 16);
        float u1 = __shfl_xor_sync(FULL, p1, 16);
        float w01 = (lane & 16) ? (p1 + u1) : (p0 + u0);
        float u2 = __shfl_xor_sync(FULL, p2, 16);
        float u3 = __shfl_xor_sync(FULL, p3, 16);
        float w23 = (lane & 16) ? (p3 + u3) : (p2 + u2);
        float v01 = __shfl_xor_sync(FULL, w01, 8);
        float v23 = __shfl_xor_sync(FULL, w23, 8);
        float v = (lane & 8) ? (w23 + v23) : (w01 + v01);
        v += __shfl_xor_sync(FULL, v, 4);
        v += __shfl_xor_sync(FULL, v, 2);
        v += __shfl_xor_sync(FULL, v, 1);
        // v = dot of row (grbase + myrow)

        const float r   = __expf(v);            // non_linearity = exp
        const float dtr = dt * r;
        float w, llc;
        if (m) {
            // 1 - e^-dtr = (E-1)/E  =>  llc = log(E-1) - dtr  (one exp)
            const float Em1 = __expf(dtr) - 1.0f;
            w   = __fdividef(dtr, Em1 - EPSF);
            llc = __logf(Em1 + EPSF) - dtr;
        } else {
            w   = -dtr;
            llc = -dtr;
        }
        const float pfmy = (myrow == 0) ? pf0 : (myrow == 1) ? pf1
                         : (myrow == 2) ? pf2 : pf3;
        p1acc += pfmy * llc;                    // 8x redundant; /8 at epilogue
        p2acc += pfmy * pfmy * llc;

        const float w0 = __shfl_sync(FULL, w, 0);
        const float w1 = __shfl_sync(FULL, w, 16);
        const float w2 = __shfl_sync(FULL, w, 8);
        const float w3 = __shfl_sync(FULL, w, 24);

        const float a0 = pf0 * w0, a1 = pf1 * w1, a2 = pf2 * w2, a3 = pf3 * w3;
        const u64 A0 = pack2(a0, a0), A1 = pack2(a1, a1);
        const u64 A2 = pack2(a2, a2), A3 = pack2(a3, a3);
        const u64 H0 = pack2(pf0 * a0, pf0 * a0), H1 = pack2(pf1 * a1, pf1 * a1);
        const u64 H2 = pack2(pf2 * a2, pf2 * a2), H3 = pack2(pf3 * a3, pf3 * a3);

        Ga01 = ffma2(A0, c0.x, Ga01); Ga23 = ffma2(A0, c0.y, Ga23);
        Ga01 = ffma2(A1, c1.x, Ga01); Ga23 = ffma2(A1, c1.y, Ga23);
        Ga01 = ffma2(A2, c2.x, Ga01); Ga23 = ffma2(A2, c2.y, Ga23);
        Ga01 = ffma2(A3, c3.x, Ga01); Ga23 = ffma2(A3, c3.y, Ga23);
        Ha01 = ffma2(H0, c0.x, Ha01); Ha23 = ffma2(H0, c0.y, Ha23);
        Ha01 = ffma2(H1, c1.x, Ha01); Ha23 = ffma2(H1, c1.y, Ha23);
        Ha01 = ffma2(H2, c2.x, Ha01); Ha23 = ffma2(H2, c2.y, Ha23);
        Ha01 = ffma2(H3, c3.x, Ha01); Ha23 = ffma2(H3, c3.y, Ha23);
    }

    #pragma unroll
    for (int o = 16; o; o >>= 1) {
        p1acc += __shfl_xor_sync(FULL, p1acc, o);
        p2acc += __shfl_xor_sync(FULL, p2acc, o);
    }
    p1acc *= 0.125f; p2acc *= 0.125f;

    if (lane < 25) {
        float g0, g1, g2, g3, h0, h1, h2, h3;
        unpack2(Ga01, g0, g1); unpack2(Ga23, g2, g3);
        unpack2(Ha01, h0, h1); unpack2(Ha23, h2, h3);
        *(float4*)&sga[warp][lane * 4] = make_float4(g0, g1, g2, g3);
        *(float4*)&sha[warp][lane * 4] = make_float4(h0, h1, h2, h3);
    }
    if (lane == 0) { sp[warp][0] = p1acc; sp[warp][1] = p2acc; }
    __syncthreads();

    if (tid < A_DIM) {
        const float ga = sga[0][tid] + sga[1][tid] + sga[2][tid] + sga[3][tid];
        const float ha = sha[0][tid] + sha[1][tid] + sha[2][tid] + sha[3][tid];
        atomicAdd(&d_acc[tid],         ga);
        atomicAdd(&d_acc[A_DIM + tid], ha);
    }
    if (tid == 0)
        atomicAdd(&d_acc[2 * A_DIM],     sp[0][0] + sp[1][0] + sp[2][0] + sp[3][0]);
    if (tid == 1)
        atomicAdd(&d_acc[2 * A_DIM + 1], sp[0][1] + sp[1][1] + sp[2][1] + sp[3][1]);

    // ---- last-block-done fused finalize ----
    __threadfence();
    __shared__ bool amlast;
    if (tid == 0) amlast = (atomicAdd(&d_done, 1u) == (unsigned)(gridDim.x - 1));
    __syncthreads();
    if (!amlast) return;

    volatile float* vacc = d_acc;
    float Ga = 0.f, Ha = 0.f;
    if (tid < A_DIM) { Ga = vacc[tid]; Ha = vacc[A_DIM + tid]; }
    const float P1 = vacc[2 * A_DIM], P2 = vacc[2 * A_DIM + 1];

    float b0 = 0.f, b1 = 0.f, b2 = 0.f, b3 = 0.f;
    for (int i = tid; i < KFR; i += 128) {
        const float pfv = phi_fr[i], pdv = phi_d[i];
        b0 += pfv; b1 += pfv * pfv; b2 += pdv; b3 += pdv * pdv;
    }
    #pragma unroll
    for (int o = 16; o; o >>= 1) {
        b0 += __shfl_xor_sync(FULL, b0, o);
        b1 += __shfl_xor_sync(FULL, b1, o);
        b2 += __shfl_xor_sync(FULL, b2, o);
        b3 += __shfl_xor_sync(FULL, b3, o);
    }
    __shared__ float shp[4][4];
    __shared__ float sc[4];
    if (lane == 0) { shp[warp][0] = b0; shp[warp][1] = b1;
                     shp[warp][2] = b2; shp[warp][3] = b3; }
    __syncthreads();

    // clean state for the next graph replay
    if (tid < A_DIM) { d_acc[tid] = 0.f; d_acc[A_DIM + tid] = 0.f; }
    if (tid == A_DIM) { d_acc[2 * A_DIM] = 0.f; d_acc[2 * A_DIM + 1] = 0.f;
                        d_done = 0u; }

    if (tid < 4) sc[tid] = shp[0][tid] + shp[1][tid] + shp[2][tid] + shp[3][tid];
    __syncthreads();

    const float S_fr = sc[0], Q_fr = sc[1], S_d = sc[2], Q_d = sc[3];
    const float n_fr = 0.5f * (float)KFR * (float)(KFR - 1);
    const float n_d  = 0.5f * (float)KD  * (float)(KD - 1);
    const float inv_kdkfr = 1.0f / ((float)KD * (float)KFR);

    if (tid == 0) {
        out[0] = (P1 * S_fr - P2) / n_fr - 2.0f * S_d * P1 * inv_kdkfr;
        out[1 + A_DIM] = (S_d * S_d - Q_d) / (2.0f * n_d)
                       + (S_fr * S_fr - Q_fr) / (2.0f * n_fr)
                       - 2.0f * S_d * S_fr * inv_kdkfr;
    }
    if (tid < A_DIM) {
        out[1 + tid] = (S_fr * Ga - Ha) / n_fr - 2.0f * S_d * Ga * inv_kdkfr;
    }
}

extern "C" void kernel_launch(void* const* d_in, const int* in_sizes, int n_in,
                              void* d_out, int out_size) {
    const float* t      = (const float*)d_in[0];
    const int*   mask   = (const int*)  d_in[1];
    const float* X      = (const float*)d_in[2];
    const float* theta  = (const float*)d_in[3];
    const float* phi_d  = (const float*)d_in[4];
    const float* phi_fr = (const float*)d_in[5];
    float* out = (float*)d_out;

    mmdglm_main<<<GRID, 128>>>(t, mask, X, theta, phi_fr, phi_d, out);
}

// round 11
// speedup vs baseline: 1.3299x; 1.0181x over previous
#include <cuda_runtime.h>
#include <cstdint>

#define T_DIM    2000
#define KFR      400
#define KD       400
#define A_DIM    100
#define RPB      3200                  // rows per block (8 t-slabs)
#define GRID     ((T_DIM * KFR) / RPB) // 250 blocks
#define NIT      25                    // macro-iters: 32 rows/warp each
#define SLOT_X   12800                 // 32 rows * 400B (one bulk DMA)
#define SLOT_SZ  12928                 // + 128B mask
#define TXB      12928u
#define OFF_TH   (4 * 2 * SLOT_SZ)                 // 103424
#define OFF_AH   (OFF_TH + 416)                    // 103840
#define OFF_MBAR (OFF_AH + 1024)                   // 104864
#define DYN_SZ   (OFF_MBAR + 64)                   // 104928
#define EPSF     1e-24f

typedef unsigned long long u64;

__device__ __forceinline__ u64 pack2(float lo, float hi) {
    u64 r; asm("mov.b64 %0, {%1, %2};" : "=l"(r) : "f"(lo), "f"(hi)); return r;
}
__device__ __forceinline__ void unpack2(u64 v, float& lo, float& hi) {
    asm("mov.b64 {%0, %1}, %2;" : "=f"(lo), "=f"(hi) : "l"(v));
}
__device__ __forceinline__ u64 ffma2(u64 a, u64 b, u64 c) {
    u64 d; asm("fma.rn.f32x2 %0, %1, %2, %3;" : "=l"(d) : "l"(a), "l"(b), "l"(c));
    return d;
}
__device__ __forceinline__ void mbar_wait(uint32_t mbar, uint32_t parity) {
    asm volatile(
        "{\n\t.reg .pred P;\n\t"
        "W_%=:\n\t"
        "mbarrier.try_wait.parity.acquire.cta.shared::cta.b64 P, [%0], %1, 0x989680;\n\t"
        "@!P bra W_%=;\n\t}"
        :: "r"(mbar), "r"(parity) : "memory");
}

// Accumulators: [0..99]=Ga, [100..199]=Ha, [200]=P1, [201]=P2. Self-cleaning.
__device__ float d_acc[2 * A_DIM + 2];
__device__ unsigned int d_done;

// One block = 3200 contiguous rows (1.28MB). Each WARP owns a contiguous
// 320KB region, consumed in 12.8KB single-DMA slots (2-deep private ring,
// per-slot mbarrier, no block sync) — 1000 coarse fully-sequential streams
// chip-wide instead of 4000 fine ones.
// Per macro-iter (32 rows): PASS 1 = row-per-lane: each lane computes the
// full 100-dot of its own row from smem (theta broadcast) — no shuffles,
// one exp/log/div lane-op serves 32 rows, per-lane exact phi_k. Lane r
// stores (A_r, H_r) = (pf*w, pf^2*w) to smem. PASS 2 = lane-per-column:
// rows re-read from smem, A/H broadcast via LDS.64, 4 FFMA2 per row.
// Fused last-block finalize.
__global__ __launch_bounds__(128) void mmdglm_main(
    const float* __restrict__ tg, const int* __restrict__ mask,
    const float* __restrict__ X, const float* __restrict__ theta,
    const float* __restrict__ phi_fr, const float* __restrict__ phi_d,
    float* __restrict__ out)
{
    extern __shared__ __align__(16) char dyn[];
    __shared__ float sga[4][A_DIM];
    __shared__ float sha[4][A_DIM];
    __shared__ float sp[4][2];

    const int warp  = threadIdx.x >> 5;
    const int lane  = threadIdx.x & 31;
    const int tid   = threadIdx.x;
    const float dt  = tg[1] - tg[0];
    const unsigned FULL = 0xffffffffu;
    const u64 Z64 = 0ull;

    const uint32_t dyn_b  = (uint32_t)__cvta_generic_to_shared(dyn);
    const uint32_t mbar_b = dyn_b + OFF_MBAR;

    // theta -> smem (broadcast table for pass 1)
    if (tid < A_DIM) *(float*)(dyn + OFF_TH + tid * 4) = __ldg(theta + tid);

    if (tid < 8) {
        asm volatile("mbarrier.init.shared.b64 [%0], 1;"
                     :: "r"(mbar_b + tid * 8) : "memory");
    }
    asm volatile("fence.proxy.async.shared::cta;" ::: "memory");
    __syncthreads();

    const char* gX = (const char*)X;
    const char* gM = (const char*)mask;
    const size_t wbase = (size_t)blockIdx.x * RPB + (size_t)warp * 800;

    auto issue = [&](int g) {
        const int slot = g & 1;
        const uint32_t sd = dyn_b + (uint32_t)(warp * 2 + slot) * SLOT_SZ;
        const uint32_t mb = mbar_b + (uint32_t)(warp * 2 + slot) * 8;
        const size_t row0 = wbase + (size_t)g * 32;
        asm volatile("mbarrier.arrive.expect_tx.shared.b64 _, [%0], %1;"
                     :: "r"(mb), "r"(TXB) : "memory");
        asm volatile("cp.async.bulk.shared::cta.global.mbarrier::complete_tx::bytes"
                     " [%0], [%1], %2, [%3];"
                     :: "r"(sd), "l"(gX + row0 * 400), "n"(SLOT_X), "r"(mb) : "memory");
        asm volatile("cp.async.bulk.shared::cta.global.mbarrier::complete_tx::bytes"
                     " [%0], [%1], %2, [%3];"
                     :: "r"(sd + SLOT_X), "l"(gM + row0 * 4), "n"(128), "r"(mb) : "memory");
    };

    if (lane == 0) { issue(0); issue(1); }

    u64 Ga01 = Z64, Ga23 = Z64, Ha01 = Z64, Ha23 = Z64;
    float p1acc = 0.f, p2acc = 0.f;

    const ulonglong2* thp = (const ulonglong2*)(dyn + OFF_TH);
    float2* ahp = (float2*)(dyn + OFF_AH) + warp * 32;

    #pragma unroll 1
    for (int g = 0; g < NIT; g++) {
        const int slot = g & 1;
        const uint32_t mb = mbar_b + (uint32_t)(warp * 2 + slot) * 8;
        mbar_wait(mb, (unsigned)((g >> 1) & 1));

        const char* sl = dyn + (warp * 2 + slot) * SLOT_SZ;

        // ---- PASS 1: row-per-lane full dot (no shuffles) ----
        const ulonglong2* myrow = (const ulonglong2*)(sl + lane * 400);
        u64 a0 = Z64, a1 = Z64, a2 = Z64, a3 = Z64;
        #pragma unroll
        for (int j = 0; j < 24; j += 2) {
            ulonglong2 x0 = myrow[j];
            ulonglong2 t0 = thp[j];
            ulonglong2 x1 = myrow[j + 1];
            ulonglong2 t1 = thp[j + 1];
            a0 = ffma2(x0.x, t0.x, a0); a1 = ffma2(x0.y, t0.y, a1);
            a2 = ffma2(x1.x, t1.x, a2); a3 = ffma2(x1.y, t1.y, a3);
        }
        { ulonglong2 x0 = myrow[24]; ulonglong2 t0 = thp[24];
          a0 = ffma2(x0.x, t0.x, a0); a1 = ffma2(x0.y, t0.y, a1); }
        float l0, h0, l1, h1, l2, h2, l3, h3;
        unpack2(a0, l0, h0); unpack2(a1, l1, h1);
        unpack2(a2, l2, h2); unpack2(a3, l3, h3);
        const float v = ((l0 + h0) + (l1 + h1)) + ((l2 + h2) + (l3 + h3));

        const int m = ((const int*)(sl + SLOT_X))[lane];

        // k = (warp*800 + g*32 + lane) % 400 ; warp*800 drops out
        int k = (g * 32) % 400 + lane;
        if (k >= KFR) k -= KFR;
        const float pf = __ldg(phi_fr + k);

        const float r   = __expf(v);            // non_linearity = exp
        const float dtr = dt * r;
        // 1 - e^-dtr = (E-1)/E  =>  llc = log(E-1) - dtr  (one exp)
        const float Em1  = __expf(dtr) - 1.0f;
        const float w_m  = __fdividef(dtr, Em1 - EPSF);
        const float ll_m = __logf(Em1 + EPSF) - dtr;
        const float w    = m ? w_m  : -dtr;
        const float llc  = m ? ll_m : -dtr;

        p1acc += pf * llc;                      // exact per-row, no redundancy
        p2acc += pf * pf * llc;
        const float A = pf * w;
        const float H = pf * A;
        ahp[lane] = make_float2(A, H);
        __syncwarp();

        // ---- PASS 2: lane-per-column accumulation (4 FFMA2 / row) ----
        if (lane < 25) {
            #pragma unroll 4
            for (int rr = 0; rr < 32; rr++) {
                const float2 ah = ahp[rr];                       // broadcast
                const ulonglong2 x =
                    ((const ulonglong2*)(sl + rr * 400))[lane];
                const u64 Au = pack2(ah.x, ah.x);
                const u64 Hu = pack2(ah.y, ah.y);
                Ga01 = ffma2(Au, x.x, Ga01); Ga23 = ffma2(Au, x.y, Ga23);
                Ha01 = ffma2(Hu, x.x, Ha01); Ha23 = ffma2(Hu, x.y, Ha23);
            }
        }
        __syncwarp();
        if (lane == 0 && g + 2 < NIT) issue(g + 2);
    }

    #pragma unroll
    for (int o = 16; o; o >>= 1) {
        p1acc += __shfl_xor_sync(FULL, p1acc, o);
        p2acc += __shfl_xor_sync(FULL, p2acc, o);
    }

    if (lane < 25) {
        float g0, g1, g2, g3, h0, h1, h2, h3;
        unpack2(Ga01, g0, g1); unpack2(Ga23, g2, g3);
        unpack2(Ha01, h0, h1); unpack2(Ha23, h2, h3);
        *(float4*)&sga[warp][lane * 4] = make_float4(g0, g1, g2, g3);
        *(float4*)&sha[warp][lane * 4] = make_float4(h0, h1, h2, h3);
    }
    if (lane == 0) { sp[warp][0] = p1acc; sp[warp][1] = p2acc; }
    __syncthreads();

    if (tid < A_DIM) {
        const float ga = sga[0][tid] + sga[1][tid] + sga[2][tid] + sga[3][tid];
        const float ha = sha[0][tid] + sha[1][tid] + sha[2][tid] + sha[3][tid];
        atomicAdd(&d_acc[tid],         ga);
        atomicAdd(&d_acc[A_DIM + tid], ha);
    }
    if (tid == 0)
        atomicAdd(&d_acc[2 * A_DIM],     sp[0][0] + sp[1][0] + sp[2][0] + sp[3][0]);
    if (tid == 1)
        atomicAdd(&d_acc[2 * A_DIM + 1], sp[0][1] + sp[1][1] + sp[2][1] + sp[3][1]);

    // ---- last-block-done fused finalize ----
    __threadfence();
    __shared__ bool amlast;
    if (tid == 0) amlast = (atomicAdd(&d_done, 1u) == (unsigned)(gridDim.x - 1));
    __syncthreads();
    if (!amlast) return;

    volatile float* vacc = d_acc;
    float Ga = 0.f, Ha = 0.f;
    if (tid < A_DIM) { Ga = vacc[tid]; Ha = vacc[A_DIM + tid]; }
    const float P1 = vacc[2 * A_DIM], P2 = vacc[2 * A_DIM + 1];

    float b0 = 0.f, b1 = 0.f, b2 = 0.f, b3 = 0.f;
    for (int i = tid; i < KFR; i += 128) {
        const float pfv = phi_fr[i], pdv = phi_d[i];
        b0 += pfv; b1 += pfv * pfv; b2 += pdv; b3 += pdv * pdv;
    }
    #pragma unroll
    for (int o = 16; o; o >>= 1) {
        b0 += __shfl_xor_sync(FULL, b0, o);
        b1 += __shfl_xor_sync(FULL, b1, o);
        b2 += __shfl_xor_sync(FULL, b2, o);
        b3 += __shfl_xor_sync(FULL, b3, o);
    }
    __shared__ float shp[4][4];
    __shared__ float sc[4];
    if (lane == 0) { shp[warp][0] = b0; shp[warp][1] = b1;
                     shp[warp][2] = b2; shp[warp][3] = b3; }
    __syncthreads();

    // clean state for the next graph replay
    if (tid < A_DIM) { d_acc[tid] = 0.f; d_acc[A_DIM + tid] = 0.f; }
    if (tid == A_DIM) { d_acc[2 * A_DIM] = 0.f; d_acc[2 * A_DIM + 1] = 0.f;
                        d_done = 0u; }

    if (tid < 4) sc[tid] = shp[0][tid] + shp[1][tid] + shp[2][tid] + shp[3][tid];
    __syncthreads();

    const float S_fr = sc[0], Q_fr = sc[1], S_d = sc[2], Q_d = sc[3];
    const float n_fr = 0.5f * (float)KFR * (float)(KFR - 1);
    const float n_d  = 0.5f * (float)KD  * (float)(KD - 1);
    const float inv_kdkfr = 1.0f / ((float)KD * (float)KFR);

    if (tid == 0) {
        out[0] = (P1 * S_fr - P2) / n_fr - 2.0f * S_d * P1 * inv_kdkfr;
        out[1 + A_DIM] = (S_d * S_d - Q_d) / (2.0f * n_d)
                       + (S_fr * S_fr - Q_fr) / (2.0f * n_fr)
                       - 2.0f * S_d * S_fr * inv_kdkfr;
    }
    if (tid < A_DIM) {
        out[1 + tid] = (S_fr * Ga - Ha) / n_fr - 2.0f * S_d * Ga * inv_kdkfr;
    }
}

extern "C" void kernel_launch(void* const* d_in, const int* in_sizes, int n_in,
                              void* d_out, int out_size) {
    const float* t      = (const float*)d_in[0];
    const int*   mask   = (const int*)  d_in[1];
    const float* X      = (const float*)d_in[2];
    const float* theta  = (const float*)d_in[3];
    const float* phi_d  = (const float*)d_in[4];
    const float* phi_fr = (const float*)d_in[5];
    float* out = (float*)d_out;

    cudaFuncSetAttribute(mmdglm_main,
                         cudaFuncAttributeMaxDynamicSharedMemorySize, DYN_SZ);
    mmdglm_main<<<GRID, 128, DYN_SZ>>>(t, mask, X, theta, phi_fr, phi_d, out);
}

// round 12
// speedup vs baseline: 1.3688x; 1.0293x over previous
#include <cuda_runtime.h>
#include <cstdint>

#define T_DIM    2000
#define KFR      400
#define KD       400
#define A_DIM    100
#define RPB      1600                  // rows per block = 4 warps x 1 t-slab
#define GRID     ((T_DIM * KFR) / RPB) // 500 blocks
#define NIT      25                    // 16-row slots per warp (400 rows)
#define SLOT_X   6400                  // 16 rows * 400B (one bulk DMA)
#define SLOT_SZ  6528                  // + 64B mask + pad (16B aligned)
#define TXB      6464u
#define OFF_TH   (4 * 2 * SLOT_SZ)                 // 52224
#define OFF_AH   (OFF_TH + 416)                    // 52640
#define OFF_MBAR (OFF_AH + 512)                    // 53152
#define DYN_SZ   (OFF_MBAR + 64)                   // 53216
#define EPSF     1e-24f

typedef unsigned long long u64;

__device__ __forceinline__ u64 pack2(float lo, float hi) {
    u64 r; asm("mov.b64 %0, {%1, %2};" : "=l"(r) : "f"(lo), "f"(hi)); return r;
}
__device__ __forceinline__ void unpack2(u64 v, float& lo, float& hi) {
    asm("mov.b64 {%0, %1}, %2;" : "=f"(lo), "=f"(hi) : "l"(v));
}
__device__ __forceinline__ u64 ffma2(u64 a, u64 b, u64 c) {
    u64 d; asm("fma.rn.f32x2 %0, %1, %2, %3;" : "=l"(d) : "l"(a), "l"(b), "l"(c));
    return d;
}
__device__ __forceinline__ void mbar_wait(uint32_t mbar, uint32_t parity) {
    asm volatile(
        "{\n\t.reg .pred P;\n\t"
        "W_%=:\n\t"
        "mbarrier.try_wait.parity.acquire.cta.shared::cta.b64 P, [%0], %1, 0x989680;\n\t"
        "@!P bra W_%=;\n\t}"
        :: "r"(mbar), "r"(parity) : "memory");
}

// Accumulators: [0..99]=Ga, [100..199]=Ha, [200]=P1, [201]=P2. Self-cleaning.
__device__ float d_acc[2 * A_DIM + 2];
__device__ unsigned int d_done;

// One block = 1600 contiguous rows; each warp owns ONE t-slab (400 rows,
// 160KB contiguous) consumed in 16-row 6.4KB single-DMA slots (2-deep
// private ring, per-slot mbarrier, no block sync). Halving the slot halves
// smem -> 4 blocks/SM, 16 warps/SM: 2x the streams of R11 at the same
// per-warp depth. PASS 1: lanes r and r+16 split row r's 100-dot (13/12
// chunks), one shfl_xor(16) merges; one exp/log/div warp-op serves 16 rows;
// per-lane exact phi_k (k = g*16 + row, no mod). (A,H)=(pf*w, pf^2*w) to
// smem. PASS 2: lane-per-column, A/H broadcast via LDS.64, 4 FFMA2/row.
// Fused last-block finalize.
__global__ __launch_bounds__(128) void mmdglm_main(
    const float* __restrict__ tg, const int* __restrict__ mask,
    const float* __restrict__ X, const float* __restrict__ theta,
    const float* __restrict__ phi_fr, const float* __restrict__ phi_d,
    float* __restrict__ out)
{
    extern __shared__ __align__(16) char dyn[];
    __shared__ float sga[4][A_DIM];
    __shared__ float sha[4][A_DIM];
    __shared__ float sp[4][2];

    const int warp  = threadIdx.x >> 5;
    const int lane  = threadIdx.x & 31;
    const int tid   = threadIdx.x;
    const float dt  = tg[1] - tg[0];
    const unsigned FULL = 0xffffffffu;
    const u64 Z64 = 0ull;

    const uint32_t dyn_b  = (uint32_t)__cvta_generic_to_shared(dyn);
    const uint32_t mbar_b = dyn_b + OFF_MBAR;

    // theta -> smem broadcast table
    if (tid < A_DIM) *(float*)(dyn + OFF_TH + tid * 4) = __ldg(theta + tid);

    if (tid < 8) {
        asm volatile("mbarrier.init.shared.b64 [%0], 1;"
                     :: "r"(mbar_b + tid * 8) : "memory");
    }
    asm volatile("fence.proxy.async.shared::cta;" ::: "memory");
    __syncthreads();

    const char* gX = (const char*)X;
    const char* gM = (const char*)mask;
    const size_t wbase = (size_t)blockIdx.x * RPB + (size_t)warp * 400;

    auto issue = [&](int g) {
        const int slot = g & 1;
        const uint32_t sd = dyn_b + (uint32_t)(warp * 2 + slot) * SLOT_SZ;
        const uint32_t mb = mbar_b + (uint32_t)(warp * 2 + slot) * 8;
        const size_t row0 = wbase + (size_t)g * 16;
        asm volatile("mbarrier.arrive.expect_tx.shared.b64 _, [%0], %1;"
                     :: "r"(mb), "r"(TXB) : "memory");
        asm volatile("cp.async.bulk.shared::cta.global.mbarrier::complete_tx::bytes"
                     " [%0], [%1], %2, [%3];"
                     :: "r"(sd), "l"(gX + row0 * 400), "n"(SLOT_X), "r"(mb) : "memory");
        asm volatile("cp.async.bulk.shared::cta.global.mbarrier::complete_tx::bytes"
                     " [%0], [%1], %2, [%3];"
                     :: "r"(sd + SLOT_X), "l"(gM + row0 * 4), "n"(64), "r"(mb) : "memory");
    };

    if (lane == 0) { issue(0); issue(1); }

    u64 Ga01 = Z64, Ga23 = Z64, Ha01 = Z64, Ha23 = Z64;
    float p1acc = 0.f, p2acc = 0.f;

    const ulonglong2* thp = (const ulonglong2*)(dyn + OFF_TH);
    float2* ahp = (float2*)(dyn + OFF_AH) + warp * 16;

    const int row    = lane & 15;           // my row within the slot
    const int cbase  = (lane < 16) ? 0 : 13;  // chunk split: 13 / 12
    const int ccount = (lane < 16) ? 13 : 12;

    #pragma unroll 1
    for (int g = 0; g < NIT; g++) {
        const int slot = g & 1;
        const uint32_t mb = mbar_b + (uint32_t)(warp * 2 + slot) * 8;
        mbar_wait(mb, (unsigned)((g >> 1) & 1));

        const char* sl = dyn + (warp * 2 + slot) * SLOT_SZ;

        // ---- PASS 1: half-row-per-lane dot ----
        const ulonglong2* myrow = (const ulonglong2*)(sl + row * 400) + cbase;
        const ulonglong2* thq   = thp + cbase;
        u64 a0 = Z64, a1 = Z64;
        #pragma unroll
        for (int j = 0; j < 12; j++) {
            ulonglong2 x = myrow[j];
            ulonglong2 t = thq[j];
            a0 = ffma2(x.x, t.x, a0); a1 = ffma2(x.y, t.y, a1);
        }
        if (ccount == 13) {
            ulonglong2 x = myrow[12];
            ulonglong2 t = thq[12];
            a0 = ffma2(x.x, t.x, a0); a1 = ffma2(x.y, t.y, a1);
        }
        float l0, h0, l1, h1;
        unpack2(a0, l0, h0); unpack2(a1, l1, h1);
        float v = (l0 + h0) + (l1 + h1);
        v += __shfl_xor_sync(FULL, v, 16);      // full 100-dot of my row

        const int m = ((const int*)(sl + SLOT_X))[row];
        const int k = g * 16 + row;             // warp/block offsets = 0 mod 400
        const float pf = __ldg(phi_fr + k);

        const float r   = __expf(v);            // non_linearity = exp
        const float dtr = dt * r;
        // 1 - e^-dtr = (E-1)/E  =>  llc = log(E-1) - dtr  (one exp)
        const float Em1  = __expf(dtr) - 1.0f;
        const float w_m  = __fdividef(dtr, Em1 - EPSF);
        const float ll_m = __logf(Em1 + EPSF) - dtr;
        const float w    = m ? w_m  : -dtr;
        const float llc  = m ? ll_m : -dtr;

        p1acc += pf * llc;                      // 2x redundant; *0.5 at end
        p2acc += pf * pf * llc;
        if (lane < 16) {
            const float A = pf * w;
            ahp[lane] = make_float2(A, pf * A);
        }
        __syncwarp();

        // ---- PASS 2: lane-per-column accumulation (4 FFMA2 / row) ----
        if (lane < 25) {
            #pragma unroll 4
            for (int rr = 0; rr < 16; rr++) {
                const float2 ah = ahp[rr];                       // broadcast
                const ulonglong2 x =
                    ((const ulonglong2*)(sl + rr * 400))[lane];
                const u64 Au = pack2(ah.x, ah.x);
                const u64 Hu = pack2(ah.y, ah.y);
                Ga01 = ffma2(Au, x.x, Ga01); Ga23 = ffma2(Au, x.y, Ga23);
                Ha01 = ffma2(Hu, x.x, Ha01); Ha23 = ffma2(Hu, x.y, Ha23);
            }
        }
        __syncwarp();
        if (lane == 0 && g + 2 < NIT) issue(g + 2);
    }

    #pragma unroll
    for (int o = 16; o; o >>= 1) {
        p1acc += __shfl_xor_sync(FULL, p1acc, o);
        p2acc += __shfl_xor_sync(FULL, p2acc, o);
    }
    p1acc *= 0.5f; p2acc *= 0.5f;

    if (lane < 25) {
        float g0, g1, g2, g3, h0, h1, h2, h3;
        unpack2(Ga01, g0, g1); unpack2(Ga23, g2, g3);
        unpack2(Ha01, h0, h1); unpack2(Ha23, h2, h3);
        *(float4*)&sga[warp][lane * 4] = make_float4(g0, g1, g2, g3);
        *(float4*)&sha[warp][lane * 4] = make_float4(h0, h1, h2, h3);
    }
    if (lane == 0) { sp[warp][0] = p1acc; sp[warp][1] = p2acc; }
    __syncthreads();

    if (tid < A_DIM) {
        const float ga = sga[0][tid] + sga[1][tid] + sga[2][tid] + sga[3][tid];
        const float ha = sha[0][tid] + sha[1][tid] + sha[2][tid] + sha[3][tid];
        atomicAdd(&d_acc[tid],         ga);
        atomicAdd(&d_acc[A_DIM + tid], ha);
    }
    if (tid == 0)
        atomicAdd(&d_acc[2 * A_DIM],     sp[0][0] + sp[1][0] + sp[2][0] + sp[3][0]);
    if (tid == 1)
        atomicAdd(&d_acc[2 * A_DIM + 1], sp[0][1] + sp[1][1] + sp[2][1] + sp[3][1]);

    // ---- last-block-done fused finalize ----
    __threadfence();
    __shared__ bool amlast;
    if (tid == 0) amlast = (atomicAdd(&d_done, 1u) == (unsigned)(gridDim.x - 1));
    __syncthreads();
    if (!amlast) return;

    volatile float* vacc = d_acc;
    float Ga = 0.f, Ha = 0.f;
    if (tid < A_DIM) { Ga = vacc[tid]; Ha = vacc[A_DIM + tid]; }
    const float P1 = vacc[2 * A_DIM], P2 = vacc[2 * A_DIM + 1];

    float b0 = 0.f, b1 = 0.f, b2 = 0.f, b3 = 0.f;
    for (int i = tid; i < KFR; i += 128) {
        const float pfv = phi_fr[i], pdv = phi_d[i];
        b0 += pfv; b1 += pfv * pfv; b2 += pdv; b3 += pdv * pdv;
    }
    #pragma unroll
    for (int o = 16; o; o >>= 1) {
        b0 += __shfl_xor_sync(FULL, b0, o);
        b1 += __shfl_xor_sync(FULL, b1, o);
        b2 += __shfl_xor_sync(FULL, b2, o);
        b3 += __shfl_xor_sync(FULL, b3, o);
    }
    __shared__ float shp[4][4];
    __shared__ float sc[4];
    if (lane == 0) { shp[warp][0] = b0; shp[warp][1] = b1;
                     shp[warp][2] = b2; shp[warp][3] = b3; }
    __syncthreads();

    // clean state for the next graph replay
    if (tid < A_DIM) { d_acc[tid] = 0.f; d_acc[A_DIM + tid] = 0.f; }
    if (tid == A_DIM) { d_acc[2 * A_DIM] = 0.f; d_acc[2 * A_DIM + 1] = 0.f;
                        d_done = 0u; }

    if (tid < 4) sc[tid] = shp[0][tid] + shp[1][tid] + shp[2][tid] + shp[3][tid];
    __syncthreads();

    const float S_fr = sc[0], Q_fr = sc[1], S_d = sc[2], Q_d = sc[3];
    const float n_fr = 0.5f * (float)KFR * (float)(KFR - 1);
    const float n_d  = 0.5f * (float)KD  * (float)(KD - 1);
    const float inv_kdkfr = 1.0f / ((float)KD * (float)KFR);

    if (tid == 0) {
        out[0] = (P1 * S_fr - P2) / n_fr - 2.0f * S_d * P1 * inv_kdkfr;
        out[1 + A_DIM] = (S_d * S_d - Q_d) / (2.0f * n_d)
                       + (S_fr * S_fr - Q_fr) / (2.0f * n_fr)
                       - 2.0f * S_d * S_fr * inv_kdkfr;
    }
    if (tid < A_DIM) {
        out[1 + tid] = (S_fr * Ga - Ha) / n_fr - 2.0f * S_d * Ga * inv_kdkfr;
    }
}

extern "C" void kernel_launch(void* const* d_in, const int* in_sizes, int n_in,
                              void* d_out, int out_size) {
    const float* t      = (const float*)d_in[0];
    const int*   mask   = (const int*)  d_in[1];
    const float* X      = (const float*)d_in[2];
    const float* theta  = (const float*)d_in[3];
    const float* phi_d  = (const float*)d_in[4];
    const float* phi_fr = (const float*)d_in[5];
    float* out = (float*)d_out;

    cudaFuncSetAttribute(mmdglm_main,
                         cudaFuncAttributeMaxDynamicSharedMemorySize, DYN_SZ);
    mmdglm_main<<<GRID, 128, DYN_SZ>>>(t, mask, X, theta, phi_fr, phi_d, out);
}

// round 13
// speedup vs baseline: 1.3971x; 1.0206x over previous
#include <cuda_runtime.h>
#include <cstdint>

#define T_DIM    2000
#define KFR      400
#define KD       400
#define A_DIM    100
#define NSLOT    50000                 // 16-row slots total (800000 rows)
#define GRID     592                   // 4 blocks/SM * 148 SMs: exactly one wave
#define NWARPS   (GRID * 4)            // 2368
#define BASEW    21                    // NSLOT / NWARPS
#define EXTRA    272                   // NSLOT - BASEW*NWARPS -> first 272 warps get 22
#define SLOT_X   6400                  // 16 rows * 400B (one bulk DMA)
#define SLOT_SZ  6528                  // + 64B mask + pad (16B aligned)
#define TXB      6464u
#define OFF_TH   (4 * 2 * SLOT_SZ)                 // 52224
#define OFF_AH   (OFF_TH + 416)                    // 52640
#define OFF_MBAR (OFF_AH + 512)                    // 53152
#define DYN_SZ   (OFF_MBAR + 64)                   // 53216
#define EPSF     1e-24f

typedef unsigned long long u64;

__device__ __forceinline__ u64 pack2(float lo, float hi) {
    u64 r; asm("mov.b64 %0, {%1, %2};" : "=l"(r) : "f"(lo), "f"(hi)); return r;
}
__device__ __forceinline__ void unpack2(u64 v, float& lo, float& hi) {
    asm("mov.b64 {%0, %1}, %2;" : "=f"(lo), "=f"(hi) : "l"(v));
}
__device__ __forceinline__ u64 ffma2(u64 a, u64 b, u64 c) {
    u64 d; asm("fma.rn.f32x2 %0, %1, %2, %3;" : "=l"(d) : "l"(a), "l"(b), "l"(c));
    return d;
}
__device__ __forceinline__ void mbar_wait(uint32_t mbar, uint32_t parity) {
    asm volatile(
        "{\n\t.reg .pred P;\n\t"
        "W_%=:\n\t"
        "mbarrier.try_wait.parity.acquire.cta.shared::cta.b64 P, [%0], %1, 0x989680;\n\t"
        "@!P bra W_%=;\n\t}"
        :: "r"(mbar), "r"(parity) : "memory");
}

// Accumulators: [0..99]=Ga, [100..199]=Ha, [200]=P1, [201]=P2. Self-cleaning.
__device__ float d_acc[2 * A_DIM + 2];
__device__ unsigned int d_done;

// Exact-capacity grid: 592 blocks = 4/SM, one perfectly-filled wave. The
// 50000 16-row slots are split statically: warp w owns 21 or 22 CONSECUTIVE
// slots (start = 21w + min(w,272)) — max imbalance 4.5% vs the 25% block-
// granular tail of a 500-block launch. Each slot: one 6.4KB bulk-DMA into a
// 2-deep private ring with per-slot mbarrier (no block sync). PASS 1: lanes
// r and r+16 split row r's 100-dot (13/12 chunks), one shfl_xor(16) merges;
// one exp/log/div warp-op serves 16 rows; per-lane exact phi_k. PASS 2:
// lane-per-column, (A,H) broadcast via LDS.64, 4 FFMA2 per row. Fused
// last-block finalize, self-cleaning for graph replay.
__global__ __launch_bounds__(128) void mmdglm_main(
    const float* __restrict__ tg, const int* __restrict__ mask,
    const float* __restrict__ X, const float* __restrict__ theta,
    const float* __restrict__ phi_fr, const float* __restrict__ phi_d,
    float* __restrict__ out)
{
    extern __shared__ __align__(16) char dyn[];
    __shared__ float sga[4][A_DIM];
    __shared__ float sha[4][A_DIM];
    __shared__ float sp[4][2];

    const int warp  = threadIdx.x >> 5;
    const int lane  = threadIdx.x & 31;
    const int tid   = threadIdx.x;
    const float dt  = tg[1] - tg[0];
    const unsigned FULL = 0xffffffffu;
    const u64 Z64 = 0ull;

    const uint32_t dyn_b  = (uint32_t)__cvta_generic_to_shared(dyn);
    const uint32_t mbar_b = dyn_b + OFF_MBAR;

    // theta -> smem broadcast table
    if (tid < A_DIM) *(float*)(dyn + OFF_TH + tid * 4) = __ldg(theta + tid);

    if (tid < 8) {
        asm volatile("mbarrier.init.shared.b64 [%0], 1;"
                     :: "r"(mbar_b + tid * 8) : "memory");
    }
    asm volatile("fence.proxy.async.shared::cta;" ::: "memory");
    __syncthreads();

    // static balanced slot range for this warp
    const int gw      = blockIdx.x * 4 + warp;
    const int myStart = BASEW * gw + (gw < EXTRA ? gw : EXTRA);
    const int myCount = BASEW + (gw < EXTRA ? 1 : 0);

    const char* gX = (const char*)X;
    const char* gM = (const char*)mask;

    auto issue = [&](int g) {
        const int slot = g & 1;
        const uint32_t sd = dyn_b + (uint32_t)(warp * 2 + slot) * SLOT_SZ;
        const uint32_t mb = mbar_b + (uint32_t)(warp * 2 + slot) * 8;
        const size_t sid = (size_t)(myStart + g);
        asm volatile("mbarrier.arrive.expect_tx.shared.b64 _, [%0], %1;"
                     :: "r"(mb), "r"(TXB) : "memory");
        asm volatile("cp.async.bulk.shared::cta.global.mbarrier::complete_tx::bytes"
                     " [%0], [%1], %2, [%3];"
                     :: "r"(sd), "l"(gX + sid * SLOT_X), "n"(SLOT_X), "r"(mb) : "memory");
        asm volatile("cp.async.bulk.shared::cta.global.mbarrier::complete_tx::bytes"
                     " [%0], [%1], %2, [%3];"
                     :: "r"(sd + SLOT_X), "l"(gM + sid * 64), "n"(64), "r"(mb) : "memory");
    };

    if (lane == 0) { issue(0); if (myCount > 1) issue(1); }

    u64 Ga01 = Z64, Ga23 = Z64, Ha01 = Z64, Ha23 = Z64;
    float p1acc = 0.f, p2acc = 0.f;

    const ulonglong2* thp = (const ulonglong2*)(dyn + OFF_TH);
    float2* ahp = (float2*)(dyn + OFF_AH) + warp * 16;

    const int row    = lane & 15;             // my row within the slot
    const int cbase  = (lane < 16) ? 0 : 13;  // chunk split: 13 / 12
    const int ccount = (lane < 16) ? 13 : 12;

    #pragma unroll 1
    for (int g = 0; g < myCount; g++) {
        const int slot = g & 1;
        const uint32_t mb = mbar_b + (uint32_t)(warp * 2 + slot) * 8;
        mbar_wait(mb, (unsigned)((g >> 1) & 1));

        const char* sl = dyn + (warp * 2 + slot) * SLOT_SZ;

        // ---- PASS 1: half-row-per-lane dot ----
        const ulonglong2* myrow = (const ulonglong2*)(sl + row * 400) + cbase;
        const ulonglong2* thq   = thp + cbase;
        u64 a0 = Z64, a1 = Z64;
        #pragma unroll
        for (int j = 0; j < 12; j++) {
            ulonglong2 x = myrow[j];
            ulonglong2 t = thq[j];
            a0 = ffma2(x.x, t.x, a0); a1 = ffma2(x.y, t.y, a1);
        }
        if (ccount == 13) {
            ulonglong2 x = myrow[12];
            ulonglong2 t = thq[12];
            a0 = ffma2(x.x, t.x, a0); a1 = ffma2(x.y, t.y, a1);
        }
        float l0, h0, l1, h1;
        unpack2(a0, l0, h0); unpack2(a1, l1, h1);
        float v = (l0 + h0) + (l1 + h1);
        v += __shfl_xor_sync(FULL, v, 16);      // full 100-dot of my row

        const int m = ((const int*)(sl + SLOT_X))[row];
        // k pattern repeats every 25 slots (25*16 = 400 rows)
        const int smod = (myStart + g) % 25;
        const int k = smod * 16 + row;
        const float pf = __ldg(phi_fr + k);

        const float r   = __expf(v);            // non_linearity = exp
        const float dtr = dt * r;
        // 1 - e^-dtr = (E-1)/E  =>  llc = log(E-1) - dtr  (one exp)
        const float Em1  = __expf(dtr) - 1.0f;
        const float w_m  = __fdividef(dtr, Em1 - EPSF);
        const float ll_m = __logf(Em1 + EPSF) - dtr;
        const float w    = m ? w_m  : -dtr;
        const float llc  = m ? ll_m : -dtr;

        p1acc += pf * llc;                      // 2x redundant; *0.5 at end
        p2acc += pf * pf * llc;
        if (lane < 16) {
            const float A = pf * w;
            ahp[lane] = make_float2(A, pf * A);
        }
        __syncwarp();

        // ---- PASS 2: lane-per-column accumulation (4 FFMA2 / row) ----
        if (lane < 25) {
            #pragma unroll 4
            for (int rr = 0; rr < 16; rr++) {
                const float2 ah = ahp[rr];                       // broadcast
                const ulonglong2 x =
                    ((const ulonglong2*)(sl + rr * 400))[lane];
                const u64 Au = pack2(ah.x, ah.x);
                const u64 Hu = pack2(ah.y, ah.y);
                Ga01 = ffma2(Au, x.x, Ga01); Ga23 = ffma2(Au, x.y, Ga23);
                Ha01 = ffma2(Hu, x.x, Ha01); Ha23 = ffma2(Hu, x.y, Ha23);
            }
        }
        __syncwarp();
        if (lane == 0 && g + 2 < myCount) issue(g + 2);
    }

    #pragma unroll
    for (int o = 16; o; o >>= 1) {
        p1acc += __shfl_xor_sync(FULL, p1acc, o);
        p2acc += __shfl_xor_sync(FULL, p2acc, o);
    }
    p1acc *= 0.5f; p2acc *= 0.5f;

    if (lane < 25) {
        float g0, g1, g2, g3, h0, h1, h2, h3;
        unpack2(Ga01, g0, g1); unpack2(Ga23, g2, g3);
        unpack2(Ha01, h0, h1); unpack2(Ha23, h2, h3);
        *(float4*)&sga[warp][lane * 4] = make_float4(g0, g1, g2, g3);
        *(float4*)&sha[warp][lane * 4] = make_float4(h0, h1, h2, h3);
    }
    if (lane == 0) { sp[warp][0] = p1acc; sp[warp][1] = p2acc; }
    __syncthreads();

    if (tid < A_DIM) {
        const float ga = sga[0][tid] + sga[1][tid] + sga[2][tid] + sga[3][tid];
        const float ha = sha[0][tid] + sha[1][tid] + sha[2][tid] + sha[3][tid];
        atomicAdd(&d_acc[tid],         ga);
        atomicAdd(&d_acc[A_DIM + tid], ha);
    }
    if (tid == 0)
        atomicAdd(&d_acc[2 * A_DIM],     sp[0][0] + sp[1][0] + sp[2][0] + sp[3][0]);
    if (tid == 1)
        atomicAdd(&d_acc[2 * A_DIM + 1], sp[0][1] + sp[1][1] + sp[2][1] + sp[3][1]);

    // ---- last-block-done fused finalize ----
    __threadfence();
    __shared__ bool amlast;
    if (tid == 0) amlast = (atomicAdd(&d_done, 1u) == (unsigned)(gridDim.x - 1));
    __syncthreads();
    if (!amlast) return;

    volatile float* vacc = d_acc;
    float Ga = 0.f, Ha = 0.f;
    if (tid < A_DIM) { Ga = vacc[tid]; Ha = vacc[A_DIM + tid]; }
    const float P1 = vacc[2 * A_DIM], P2 = vacc[2 * A_DIM + 1];

    float b0 = 0.f, b1 = 0.f, b2 = 0.f, b3 = 0.f;
    for (int i = tid; i < KFR; i += 128) {
        const float pfv = phi_fr[i], pdv = phi_d[i];
        b0 += pfv; b1 += pfv * pfv; b2 += pdv; b3 += pdv * pdv;
    }
    #pragma unroll
    for (int o = 16; o; o >>= 1) {
        b0 += __shfl_xor_sync(FULL, b0, o);
        b1 += __shfl_xor_sync(FULL, b1, o);
        b2 += __shfl_xor_sync(FULL, b2, o);
        b3 += __shfl_xor_sync(FULL, b3, o);
    }
    __shared__ float shp[4][4];
    __shared__ float sc[4];
    if (lane == 0) { shp[warp][0] = b0; shp[warp][1] = b1;
                     shp[warp][2] = b2; shp[warp][3] = b3; }
    __syncthreads();

    // clean state for the next graph replay
    if (tid < A_DIM) { d_acc[tid] = 0.f; d_acc[A_DIM + tid] = 0.f; }
    if (tid == A_DIM) { d_acc[2 * A_DIM] = 0.f; d_acc[2 * A_DIM + 1] = 0.f;
                        d_done = 0u; }

    if (tid < 4) sc[tid] = shp[0][tid] + shp[1][tid] + shp[2][tid] + shp[3][tid];
    __syncthreads();

    const float S_fr = sc[0], Q_fr = sc[1], S_d = sc[2], Q_d = sc[3];
    const float n_fr = 0.5f * (float)KFR * (float)(KFR - 1);
    const float n_d  = 0.5f * (float)KD  * (float)(KD - 1);
    const float inv_kdkfr = 1.0f / ((float)KD * (float)KFR);

    if (tid == 0) {
        out[0] = (P1 * S_fr - P2) / n_fr - 2.0f * S_d * P1 * inv_kdkfr;
        out[1 + A_DIM] = (S_d * S_d - Q_d) / (2.0f * n_d)
                       + (S_fr * S_fr - Q_fr) / (2.0f * n_fr)
                       - 2.0f * S_d * S_fr * inv_kdkfr;
    }
    if (tid < A_DIM) {
        out[1 + tid] = (S_fr * Ga - Ha) / n_fr - 2.0f * S_d * Ga * inv_kdkfr;
    }
}

extern "C" void kernel_launch(void* const* d_in, const int* in_sizes, int n_in,
                              void* d_out, int out_size) {
    const float* t      = (const float*)d_in[0];
    const int*   mask   = (const int*)  d_in[1];
    const float* X      = (const float*)d_in[2];
    const float* theta  = (const float*)d_in[3];
    const float* phi_d  = (const float*)d_in[4];
    const float* phi_fr = (const float*)d_in[5];
    float* out = (float*)d_out;

    cudaFuncSetAttribute(mmdglm_main,
                         cudaFuncAttributeMaxDynamicSharedMemorySize, DYN_SZ);
    mmdglm_main<<<GRID, 128, DYN_SZ>>>(t, mask, X, theta, phi_fr, phi_d, out);
}